// round 2
// baseline (speedup 1.0000x reference)
#include <cuda_runtime.h>
#include <math.h>

// Problem constants
#define BSZ   16
#define LSZ   2048
#define HSZ   768
#define NEN   64
#define SPAN  4
#define NPAIR 2016                 // 64*63/2
#define NROWS (BSZ*NPAIR)          // 32256
#define H2DIM 512
#define H3DIM 256

// ---------------- scratch (static device allocations; no runtime alloc) ------
__device__ __align__(16) float d_emb[BSZ*NEN*HSZ];   // raw span-max embeddings
__device__ __align__(16) float d_nrm[BSZ*NEN*HSZ];   // normalized embeddings
__device__ __align__(16) float d_cos[BSZ*NEN*NEN];
__device__ float d_std[BSZ];
__device__ int   d_pi[NPAIR];
__device__ int   d_pj[NPAIR];
__device__ __align__(16) float d_G1[BSZ*NEN*HSZ];    // emb @ w1[1:769]
__device__ __align__(16) float d_G2[BSZ*NEN*HSZ];    // emb @ w1[769:1537]
__device__ __align__(16) float d_H1[(size_t)NROWS*HSZ];
__device__ __align__(16) float d_H2[(size_t)NROWS*H2DIM];
__device__ __align__(16) float d_H3[(size_t)NROWS*H3DIM];

// ---------------- K1: span max-pool + L2 normalize ---------------------------
__global__ void k_emb(const float* __restrict__ x, const int* __restrict__ starts) {
    int be = blockIdx.x;                 // 0..B*NE-1
    int b  = be / NEN;
    int e  = be - b*NEN;
    int s0 = starts[b*NEN + e];
    const float* xb = x + ((size_t)b*LSZ + s0) * HSZ;
    int t = threadIdx.x;                 // 256 threads, 3 elems each
    float v[3];
    float ss = 0.f;
#pragma unroll
    for (int r = 0; r < 3; r++) {
        int c = t + r*256;
        float m = xb[c];
        m = fmaxf(m, xb[HSZ   + c]);
        m = fmaxf(m, xb[2*HSZ + c]);
        m = fmaxf(m, xb[3*HSZ + c]);
        v[r] = m;
        ss += m*m;
    }
    __shared__ float red[256];
    red[t] = ss;
    __syncthreads();
    for (int o = 128; o > 0; o >>= 1) {
        if (t < o) red[t] += red[t + o];
        __syncthreads();
    }
    __shared__ float s_inv;
    if (t == 0) s_inv = 1.0f / fmaxf(sqrtf(red[0]), 1e-8f);
    __syncthreads();
    float iv = s_inv;
#pragma unroll
    for (int r = 0; r < 3; r++) {
        int c = t + r*256;
        d_emb[be*HSZ + c] = v[r];
        d_nrm[be*HSZ + c] = v[r] * iv;
    }
}

// ---------------- K2: pair index tables (triu order, i-major) ---------------
__global__ void k_pairs() {
    int i = threadIdx.x;                 // 64 threads
    if (i >= NEN - 1) return;
    int off = i * (2*NEN - 1 - i) / 2;   // = i*63 - i*(i-1)/2
    for (int j = i + 1; j < NEN; j++) {
        d_pi[off] = i;
        d_pj[off] = j;
        off++;
    }
}

// ---------------- K3: cosine matrix (full NExNE per batch) -------------------
__global__ void k_cos() {
    int i = blockIdx.x;                  // entity i
    int b = blockIdx.y;                  // batch
    __shared__ float ni[HSZ];
    int t = threadIdx.x;                 // 256
    const float* base = d_nrm + (b*NEN + i)*HSZ;
#pragma unroll
    for (int r = 0; r < 3; r++) ni[t + r*256] = base[t + r*256];
    __syncthreads();
    int warp = t >> 5, lane = t & 31;
    for (int j = warp; j < NEN; j += 8) {
        const float* nj = d_nrm + (b*NEN + j)*HSZ;
        float s = 0.f;
        for (int c = lane; c < HSZ; c += 32) s += ni[c] * nj[c];
#pragma unroll
        for (int o = 16; o; o >>= 1) s += __shfl_xor_sync(0xffffffffu, s, o);
        if (lane == 0) d_cos[(b*NEN + i)*NEN + j] = s;
    }
}

// ---------------- K4: unbiased std per batch (double accum) ------------------
__global__ void k_std() {
    int b = blockIdx.x;
    int t = threadIdx.x;                 // 256
    double s = 0.0, s2 = 0.0;
    for (int k = t; k < NEN*NEN; k += 256) {
        double v = (double)d_cos[b*NEN*NEN + k];
        s  += v;
        s2 += v*v;
    }
    __shared__ double rs[256], rq[256];
    rs[t] = s; rq[t] = s2;
    __syncthreads();
    for (int o = 128; o > 0; o >>= 1) {
        if (t < o) { rs[t] += rs[t+o]; rq[t] += rq[t+o]; }
        __syncthreads();
    }
    if (t == 0) {
        double n = (double)(NEN*NEN);
        double var = (rq[0] - rs[0]*rs[0]/n) / (n - 1.0);
        if (var < 0.0) var = 0.0;
        d_std[b] = (float)sqrt(var);
    }
}

// ---------------- generic fp32 SGEMM: C = act(A@B + bias) --------------------
// A row-major MxK (selected from scratch), B row-major KxN, C row-major MxN.
// BM=BN=128, BK=16, 256 threads, 8x8 per thread. All dims divisible.
__device__ __forceinline__ const float* sel_A(int s) {
    return s == 0 ? d_emb : (s == 1 ? d_H1 : d_H2);
}
__device__ __forceinline__ float* sel_C(int s) {
    return s == 0 ? d_G1 : (s == 1 ? d_G2 : (s == 2 ? d_H2 : d_H3));
}

__global__ __launch_bounds__(256) void sgemm(int selA, const float* __restrict__ Bw,
                                             const float* __restrict__ bias, int selC,
                                             int M, int N, int K, int act) {
    const float* A = sel_A(selA);
    float* C = sel_C(selC);

    __shared__ float As[16][128];        // transposed A tile
    __shared__ float Bs[16][128];

    int bm = blockIdx.y * 128;
    int bn = blockIdx.x * 128;
    int tid = threadIdx.x;
    int tx = tid & 15;                   // 0..15 (n)
    int ty = tid >> 4;                   // 0..15 (m)

    int arow =  tid >> 2;                // 0..63
    int acol = (tid & 3) * 4;            // 0,4,8,12
    int brow =  tid >> 5;                // 0..7
    int bcol = (tid & 31) * 4;           // 0..124

    float acc[8][8];
#pragma unroll
    for (int i = 0; i < 8; i++)
#pragma unroll
        for (int j = 0; j < 8; j++) acc[i][j] = 0.f;

    for (int k0 = 0; k0 < K; k0 += 16) {
        float4 a0 = *(const float4*)&A[(size_t)(bm + arow     )*K + k0 + acol];
        float4 a1 = *(const float4*)&A[(size_t)(bm + arow + 64)*K + k0 + acol];
        As[acol+0][arow]      = a0.x; As[acol+1][arow]      = a0.y;
        As[acol+2][arow]      = a0.z; As[acol+3][arow]      = a0.w;
        As[acol+0][arow + 64] = a1.x; As[acol+1][arow + 64] = a1.y;
        As[acol+2][arow + 64] = a1.z; As[acol+3][arow + 64] = a1.w;

        float4 b0 = *(const float4*)&Bw[(size_t)(k0 + brow    )*N + bn + bcol];
        float4 b1 = *(const float4*)&Bw[(size_t)(k0 + brow + 8)*N + bn + bcol];
        *(float4*)&Bs[brow    ][bcol] = b0;
        *(float4*)&Bs[brow + 8][bcol] = b1;
        __syncthreads();

#pragma unroll
        for (int kk = 0; kk < 16; kk++) {
            float af[8], bf[8];
            *(float4*)&af[0] = *(const float4*)&As[kk][ty*8];
            *(float4*)&af[4] = *(const float4*)&As[kk][ty*8 + 4];
            *(float4*)&bf[0] = *(const float4*)&Bs[kk][tx*8];
            *(float4*)&bf[4] = *(const float4*)&Bs[kk][tx*8 + 4];
#pragma unroll
            for (int i = 0; i < 8; i++)
#pragma unroll
                for (int j = 0; j < 8; j++) acc[i][j] = fmaf(af[i], bf[j], acc[i][j]);
        }
        __syncthreads();
    }

#pragma unroll
    for (int i = 0; i < 8; i++) {
        int row = bm + ty*8 + i;
#pragma unroll
        for (int j4 = 0; j4 < 8; j4 += 4) {
            int col = bn + tx*8 + j4;
            float4 v;
            float b0 = bias ? bias[col+0] : 0.f;
            float b1 = bias ? bias[col+1] : 0.f;
            float b2 = bias ? bias[col+2] : 0.f;
            float b3 = bias ? bias[col+3] : 0.f;
            v.x = acc[i][j4+0] + b0;
            v.y = acc[i][j4+1] + b1;
            v.z = acc[i][j4+2] + b2;
            v.w = acc[i][j4+3] + b3;
            if (act) {
                v.x = fmaxf(v.x, 0.f); v.y = fmaxf(v.y, 0.f);
                v.z = fmaxf(v.z, 0.f); v.w = fmaxf(v.w, 0.f);
            }
            *(float4*)&C[(size_t)row*N + col] = v;
        }
    }
}

// ---------------- K5: assemble H1 = relu(G1_i + G2_j + sim*w1row0 + b1) ------
__global__ void k_h1(const float* __restrict__ w1, const float* __restrict__ b1,
                     const float* __restrict__ thr) {
    int r = blockIdx.x;                  // 0..NROWS-1
    int b = r / NPAIR;
    int p = r - b*NPAIR;
    int i = d_pi[p], j = d_pj[p];
    float sim = (d_cos[(b*NEN + i)*NEN + j] - thr[0]) / (d_std[b] + 1e-5f);
    const float* g1 = d_G1 + (size_t)(b*NEN + i)*HSZ;
    const float* g2 = d_G2 + (size_t)(b*NEN + j)*HSZ;
    float* out = d_H1 + (size_t)r*HSZ;
    int t = threadIdx.x;                 // 256
#pragma unroll
    for (int rr = 0; rr < 3; rr++) {
        int c = t + rr*256;
        float v = g1[c] + g2[c] + sim * w1[c] + b1[c];
        out[c] = fmaxf(v, 0.f);
    }
}

// ---------------- K6: final tiny layer: out = H3 @ w4 + b4 -------------------
__global__ void k_out(const float* __restrict__ w4, const float* __restrict__ b4,
                      float* __restrict__ out) {
    __shared__ float w[H3DIM*2];
    int t = threadIdx.x;                 // 256
    w[t]       = w4[t];
    w[t + 256] = w4[t + 256];
    __syncthreads();
    int warp = t >> 5, lane = t & 31;
    int r = blockIdx.x*8 + warp;
    const float* h = d_H3 + (size_t)r*H3DIM;
    float s0 = 0.f, s1 = 0.f;
    for (int c = lane; c < H3DIM; c += 32) {
        float hv = h[c];
        s0 = fmaf(hv, w[c*2+0], s0);
        s1 = fmaf(hv, w[c*2+1], s1);
    }
#pragma unroll
    for (int o = 16; o; o >>= 1) {
        s0 += __shfl_xor_sync(0xffffffffu, s0, o);
        s1 += __shfl_xor_sync(0xffffffffu, s1, o);
    }
    if (lane == 0) {
        out[r*2 + 0] = s0 + b4[0];
        out[r*2 + 1] = s1 + b4[1];
    }
}

// ---------------- launch ----------------------------------------------------
extern "C" void kernel_launch(void* const* d_in, const int* in_sizes, int n_in,
                              void* d_out, int out_size) {
    const float* x      = (const float*)d_in[0];
    const float* thr    = (const float*)d_in[1];
    const float* w1     = (const float*)d_in[2];
    const float* b1     = (const float*)d_in[3];
    const float* w2     = (const float*)d_in[4];
    const float* b2     = (const float*)d_in[5];
    const float* w3     = (const float*)d_in[6];
    const float* b3     = (const float*)d_in[7];
    const float* w4     = (const float*)d_in[8];
    const float* b4     = (const float*)d_in[9];
    const int*   starts = (const int*)d_in[10];
    float* out = (float*)d_out;

    // embeddings + normalization
    k_emb<<<BSZ*NEN, 256>>>(x, starts);
    k_pairs<<<1, 64>>>();
    dim3 gcos(NEN, BSZ);
    k_cos<<<gcos, 256>>>();
    k_std<<<BSZ, 256>>>();

    // G1 = emb @ w1[1:769], G2 = emb @ w1[769:1537]   (M=1024, N=768, K=768)
    {
        dim3 g(HSZ/128, (BSZ*NEN)/128);  // (6, 8)
        sgemm<<<g, 256>>>(0, w1 + (size_t)1*HSZ,   nullptr, 0, BSZ*NEN, HSZ, HSZ, 0);
        sgemm<<<g, 256>>>(0, w1 + (size_t)769*HSZ, nullptr, 1, BSZ*NEN, HSZ, HSZ, 0);
    }

    // H1 assembly (layer 1 factored)
    k_h1<<<NROWS, 256>>>(w1, b1, thr);

    // layer 2: H2 = relu(H1 @ w2 + b2)   (32256 x 768 x 512)
    {
        dim3 g(H2DIM/128, NROWS/128);    // (4, 252)
        sgemm<<<g, 256>>>(1, w2, b2, 2, NROWS, H2DIM, HSZ, 1);
    }
    // layer 3: H3 = relu(H2 @ w3 + b3)   (32256 x 512 x 256)
    {
        dim3 g(H3DIM/128, NROWS/128);    // (2, 252)
        sgemm<<<g, 256>>>(2, w3, b3, 3, NROWS, H3DIM, H2DIM, 1);
    }
    // layer 4: out = H3 @ w4 + b4
    k_out<<<NROWS/8, 256>>>(w4, b4, out);
}

// round 7
// speedup vs baseline: 2.0423x; 2.0423x over previous
#include <cuda_runtime.h>
#include <cuda_bf16.h>
#include <math.h>
#include <stdint.h>

// Problem constants
#define BSZ   16
#define LSZ   2048
#define HSZ   768
#define NEN   64
#define SPAN  4
#define NPAIR 2016
#define NROWS (BSZ*NPAIR)          // 32256
#define H2DIM 512
#define H3DIM 256
#define K1X   (3*HSZ)              // 2304  planes [h | l | h] (A) / [h | h | l] (B)
#define K2X   (3*H2DIM)            // 1536

// ---------------- scratch (device globals; resolved ONLY in device code) -----
__device__ __align__(16) float d_nrm[BSZ*NEN*HSZ];
__device__ __align__(16) float d_cos[BSZ*NEN*NEN];
__device__ float d_std[BSZ];
__device__ int   d_pi[NPAIR];
__device__ int   d_pj[NPAIR];
__device__ __align__(16) __nv_bfloat16 d_embX[BSZ*NEN*K1X];        // [1024][2304]
__device__ __align__(16) __nv_bfloat16 d_w1x [1536*K1X];           // [1536][2304]
__device__ __align__(16) __nv_bfloat16 d_w2x [H2DIM*K1X];          // [512][2304]
__device__ __align__(16) __nv_bfloat16 d_w3x [H3DIM*K2X];          // [256][1536]
__device__ __align__(16) float d_G [(size_t)BSZ*NEN*1536];         // [G1|G2]
__device__ __align__(16) __nv_bfloat16 d_H1x[(size_t)NROWS*K1X];
__device__ __align__(16) __nv_bfloat16 d_H2x[(size_t)NROWS*K2X];
__device__ __align__(16) float d_H3[(size_t)NROWS*H3DIM];

// device-side pointer selectors (NEVER pass __device__ globals from host!)
__device__ __forceinline__ const __nv_bfloat16* selA(int s) {
    return s == 0 ? d_embX : (s == 1 ? d_H1x : d_H2x);
}
__device__ __forceinline__ const __nv_bfloat16* selB(int s) {
    return s == 0 ? d_w1x : (s == 1 ? d_w2x : d_w3x);
}
__device__ __forceinline__ __nv_bfloat16* selWout(int s) {
    return s == 1 ? d_w2x : d_w3x;
}

// ---------------- helpers ----------------------------------------------------
__device__ __forceinline__ uint32_t smem_u32(const void* p) {
    return (uint32_t)__cvta_generic_to_shared(p);
}
#define CP16(dst, src) asm volatile("cp.async.cg.shared.global [%0], [%1], 16;\n" :: "r"(dst), "l"(src))
#define CP_COMMIT()    asm volatile("cp.async.commit_group;\n" ::: "memory")
#define CP_WAIT1()     asm volatile("cp.async.wait_group 1;\n" ::: "memory")
#define CP_WAIT0()     asm volatile("cp.async.wait_group 0;\n" ::: "memory")

__device__ __forceinline__ uint32_t pack_bf2(__nv_bfloat16 a, __nv_bfloat16 b) {
    __nv_bfloat162 t = __nv_bfloat162(a, b);    // a = low 16 bits
    uint32_t u; memcpy(&u, &t, 4); return u;
}
__device__ __forceinline__ void split_bf(float v, __nv_bfloat16& h, __nv_bfloat16& l) {
    h = __float2bfloat16_rn(v);
    l = __float2bfloat16_rn(v - __bfloat162float(h));
}

// ---------------- K1: span max-pool + normalize + plane split ----------------
__global__ void k_emb(const float* __restrict__ x, const int* __restrict__ starts) {
    int be = blockIdx.x;
    int b  = be / NEN;
    int e  = be - b*NEN;
    int s0 = starts[b*NEN + e];
    const float* xb = x + ((size_t)b*LSZ + s0) * HSZ;
    int t = threadIdx.x;                 // 256
    float v[3];
    float ss = 0.f;
#pragma unroll
    for (int r = 0; r < 3; r++) {
        int c = t + r*256;
        float m = xb[c];
        m = fmaxf(m, xb[HSZ   + c]);
        m = fmaxf(m, xb[2*HSZ + c]);
        m = fmaxf(m, xb[3*HSZ + c]);
        v[r] = m;
        ss += m*m;
    }
    __shared__ float red[256];
    red[t] = ss;
    __syncthreads();
    for (int o = 128; o > 0; o >>= 1) {
        if (t < o) red[t] += red[t + o];
        __syncthreads();
    }
    __shared__ float s_inv;
    if (t == 0) s_inv = 1.0f / fmaxf(sqrtf(red[0]), 1e-8f);
    __syncthreads();
    float iv = s_inv;
    __nv_bfloat16* ex = d_embX + (size_t)be*K1X;
#pragma unroll
    for (int r = 0; r < 3; r++) {
        int c = t + r*256;
        d_nrm[be*HSZ + c] = v[r] * iv;
        __nv_bfloat16 h, l; split_bf(v[r], h, l);
        ex[c]         = h;              // plane 0: high
        ex[HSZ   + c] = l;              // plane 1: low
        ex[2*HSZ + c] = h;              // plane 2: high
    }
}

// ---------------- K2: pair tables --------------------------------------------
__global__ void k_pairs() {
    int i = threadIdx.x;
    if (i >= NEN - 1) return;
    int off = i*63 - i*(i-1)/2;
    for (int j = i + 1; j < NEN; j++) { d_pi[off] = i; d_pj[off] = j; off++; }
}

// ---------------- K3: cosine matrix ------------------------------------------
__global__ void k_cos() {
    int i = blockIdx.x, b = blockIdx.y;
    __shared__ float ni[HSZ];
    int t = threadIdx.x;
    const float* base = d_nrm + (b*NEN + i)*HSZ;
#pragma unroll
    for (int r = 0; r < 3; r++) ni[t + r*256] = base[t + r*256];
    __syncthreads();
    int warp = t >> 5, lane = t & 31;
    for (int j = warp; j < NEN; j += 8) {
        const float* nj = d_nrm + (b*NEN + j)*HSZ;
        float s = 0.f;
        for (int c = lane; c < HSZ; c += 32) s += ni[c] * nj[c];
#pragma unroll
        for (int o = 16; o; o >>= 1) s += __shfl_xor_sync(0xffffffffu, s, o);
        if (lane == 0) d_cos[(b*NEN + i)*NEN + j] = s;
    }
}

// ---------------- K4: unbiased std -------------------------------------------
__global__ void k_std() {
    int b = blockIdx.x, t = threadIdx.x;
    double s = 0.0, s2 = 0.0;
    for (int k = t; k < NEN*NEN; k += 256) {
        double v = (double)d_cos[b*NEN*NEN + k];
        s += v; s2 += v*v;
    }
    __shared__ double rs[256], rq[256];
    rs[t] = s; rq[t] = s2;
    __syncthreads();
    for (int o = 128; o > 0; o >>= 1) {
        if (t < o) { rs[t] += rs[t+o]; rq[t] += rq[t+o]; }
        __syncthreads();
    }
    if (t == 0) {
        double n = (double)(NEN*NEN);
        double var = (rq[0] - rs[0]*rs[0]/n) / (n - 1.0);
        if (var < 0.0) var = 0.0;
        d_std[b] = (float)sqrt(var);
    }
}

// ---------------- transposed weight plane expansion --------------------------
// W: [K][N] row-major -> Out(sel): [N][3K] planes [h | h | l].
__global__ void k_expand_t(const float* __restrict__ W, int selOut, int K, int N) {
    __nv_bfloat16* Out = selWout(selOut);
    int idx = blockIdx.x*256 + threadIdx.x;
    if (idx >= K*N) return;
    int n = idx / K, k = idx - n*K;
    __nv_bfloat16 h, l; split_bf(W[(size_t)k*N + n], h, l);
    __nv_bfloat16* o = Out + (size_t)n*3*K;
    o[k]       = h;                     // pairs with A high
    o[K + k]   = h;                     // pairs with A low
    o[2*K + k] = l;                     // pairs with A high
}
// combined [w1a | w1b] transposed planes -> d_w1x [1536][2304] (device-side)
__global__ void k_expand_w1_t(const float* __restrict__ w1) {
    int idx = blockIdx.x*256 + threadIdx.x;
    if (idx >= 1536*HSZ) return;
    int n = idx / HSZ, k = idx - n*HSZ;
    float v = (n < HSZ) ? w1[(size_t)(1+k)*HSZ + n]
                        : w1[(size_t)(769+k)*HSZ + (n-HSZ)];
    __nv_bfloat16 h, l; split_bf(v, h, l);
    __nv_bfloat16* o = d_w1x + (size_t)n*K1X;
    o[k]         = h;
    o[HSZ + k]   = h;
    o[2*HSZ + k] = l;
}

// ---------------- bf16 tensor-core GEMM (cp.async double-buffer) -------------
// outMode 0: Cf=d_G (no relu).  1: Cx=d_H2x split planes (relu).  2: Cf=d_H3 (relu).
// A(selA_i): [M][Kx] row-major.  B(selB_i): [N][Kx] row-major (transposed weights).
// BM=BN=128, BK=32, 256 threads, warp tile 64x32.
__global__ __launch_bounds__(256, 2)
void gemm_bf16(int selA_i, int selB_i, const float* __restrict__ bias,
               int outMode, int M, int N, int Kx) {
    const __nv_bfloat16* A  = selA(selA_i);
    const __nv_bfloat16* Bt = selB(selB_i);
    float* Cf = (outMode == 0) ? d_G : d_H3;
    __nv_bfloat16* Cx = (outMode == 1) ? d_H2x : nullptr;
    int relu = (outMode != 0);

    __shared__ __align__(16) __nv_bfloat16 As[2][128][40];
    __shared__ __align__(16) __nv_bfloat16 Bs[2][128][40];

    int tid = threadIdx.x;
    int bm = blockIdx.y * 128;
    int bn = blockIdx.x * 128;
    int lane = tid & 31, w = tid >> 5;
    int wm = w & 1, wn = w >> 1;
    const int m_off = wm*64, n_off = wn*32;
    int gid = lane >> 2, tig = lane & 3;

    float acc[4][4][4];
#pragma unroll
    for (int i = 0; i < 4; i++)
#pragma unroll
        for (int j = 0; j < 4; j++)
#pragma unroll
            for (int q = 0; q < 4; q++) acc[i][j][q] = 0.f;

    int nk = Kx >> 5;

    // prefetch tile 0
#pragma unroll
    for (int rr = 0; rr < 2; rr++) {
        int q = tid + rr*256;
        int row = q >> 2, c8 = (q & 3)*8;
        CP16(smem_u32(&As[0][row][c8]), A  + (size_t)(bm + row)*Kx + c8);
        CP16(smem_u32(&Bs[0][row][c8]), Bt + (size_t)(bn + row)*Kx + c8);
    }
    CP_COMMIT();

    for (int kt = 0; kt < nk; kt++) {
        int cur = kt & 1;
        if (kt + 1 < nk) {
            int k0 = (kt + 1) << 5;
            int nxt = cur ^ 1;
#pragma unroll
            for (int rr = 0; rr < 2; rr++) {
                int q = tid + rr*256;
                int row = q >> 2, c8 = (q & 3)*8;
                CP16(smem_u32(&As[nxt][row][c8]), A  + (size_t)(bm + row)*Kx + k0 + c8);
                CP16(smem_u32(&Bs[nxt][row][c8]), Bt + (size_t)(bn + row)*Kx + k0 + c8);
            }
            CP_COMMIT();
            CP_WAIT1();          // tile kt's group done; tile kt+1 in flight
        } else {
            CP_WAIT0();          // tail: drain everything
        }
        __syncthreads();

#pragma unroll
        for (int kk = 0; kk < 2; kk++) {
            int kc = kk*16 + tig*2;
            uint32_t af[4][4];
#pragma unroll
            for (int mi = 0; mi < 4; mi++) {
                const __nv_bfloat16* pa = &As[cur][m_off + mi*16 + gid][kc];
                af[mi][0] = *(const uint32_t*)(pa);            // row gid,   k kc
                af[mi][1] = *(const uint32_t*)(pa + 8*40);     // row gid+8, k kc
                af[mi][2] = *(const uint32_t*)(pa + 8);        // row gid,   k kc+8
                af[mi][3] = *(const uint32_t*)(pa + 8*40 + 8); // row gid+8, k kc+8
            }
            uint32_t bf[4][2];
#pragma unroll
            for (int nj = 0; nj < 4; nj++) {
                const __nv_bfloat16* pb = &Bs[cur][n_off + nj*8 + gid][kc];
                bf[nj][0] = *(const uint32_t*)(pb);            // n gid, k kc
                bf[nj][1] = *(const uint32_t*)(pb + 8);        // n gid, k kc+8
            }
#pragma unroll
            for (int mi = 0; mi < 4; mi++)
#pragma unroll
                for (int nj = 0; nj < 4; nj++) {
                    asm volatile(
                        "mma.sync.aligned.m16n8k16.row.col.f32.bf16.bf16.f32 "
                        "{%0,%1,%2,%3}, {%4,%5,%6,%7}, {%8,%9}, {%0,%1,%2,%3};"
                        : "+f"(acc[mi][nj][0]), "+f"(acc[mi][nj][1]),
                          "+f"(acc[mi][nj][2]), "+f"(acc[mi][nj][3])
                        : "r"(af[mi][0]), "r"(af[mi][1]), "r"(af[mi][2]), "r"(af[mi][3]),
                          "r"(bf[nj][0]), "r"(bf[nj][1]));
                }
        }
        __syncthreads();
    }

    // epilogue
#pragma unroll
    for (int mi = 0; mi < 4; mi++) {
        int r0 = bm + m_off + mi*16 + gid;
#pragma unroll
        for (int nj = 0; nj < 4; nj++) {
            int c = bn + n_off + nj*8 + tig*2;
            float bb0 = bias ? bias[c]   : 0.f;
            float bb1 = bias ? bias[c+1] : 0.f;
#pragma unroll
            for (int half = 0; half < 2; half++) {
                int r = r0 + half*8;
                float v0 = acc[mi][nj][half*2+0] + bb0;
                float v1 = acc[mi][nj][half*2+1] + bb1;
                if (relu) { v0 = fmaxf(v0, 0.f); v1 = fmaxf(v1, 0.f); }
                if (Cx) {
                    // plane-split row of length 3N: [h | l | h]
                    __nv_bfloat16 h0, l0, h1, l1;
                    split_bf(v0, h0, l0);
                    split_bf(v1, h1, l1);
                    uint32_t* po = (uint32_t*)Cx;
                    size_t rb = (size_t)r*3*N;
                    po[(rb +       c) >> 1] = pack_bf2(h0, h1);
                    po[(rb +   N + c) >> 1] = pack_bf2(l0, l1);
                    po[(rb + 2*N + c) >> 1] = pack_bf2(h0, h1);
                } else {
                    float2 v; v.x = v0; v.y = v1;
                    *(float2*)&Cf[(size_t)r*N + c] = v;
                }
            }
        }
    }
}

// ---------------- K5: assemble plane-split H1 --------------------------------
__global__ void k_h1(const float* __restrict__ w1, const float* __restrict__ b1,
                     const float* __restrict__ thr) {
    int r = blockIdx.x;
    int b = r / NPAIR;
    int p = r - b*NPAIR;
    int i = d_pi[p], j = d_pj[p];
    float sim = (d_cos[(b*NEN + i)*NEN + j] - thr[0]) / (d_std[b] + 1e-5f);
    const float* g1 = d_G + (size_t)(b*NEN + i)*1536;
    const float* g2 = d_G + (size_t)(b*NEN + j)*1536 + HSZ;
    uint32_t* po = (uint32_t*)(d_H1x + (size_t)r*K1X);
    int pidx = threadIdx.x;              // 384 threads, one col-pair each
    int c = pidx*2;
    float v0 = fmaxf(g1[c]   + g2[c]   + sim*w1[c]   + b1[c],   0.f);
    float v1 = fmaxf(g1[c+1] + g2[c+1] + sim*w1[c+1] + b1[c+1], 0.f);
    __nv_bfloat16 h0, l0, h1, l1;
    split_bf(v0, h0, l0);
    split_bf(v1, h1, l1);
    po[pidx]              = pack_bf2(h0, h1);  // plane 0 (high)
    po[(HSZ >> 1) + pidx] = pack_bf2(l0, l1);  // plane 1 (low)
    po[HSZ + pidx]        = pack_bf2(h0, h1);  // plane 2 (high)
}

// ---------------- K6: final tiny layer ---------------------------------------
__global__ void k_out(const float* __restrict__ w4, const float* __restrict__ b4,
                      float* __restrict__ out) {
    __shared__ float wsh[H3DIM*2];
    int t = threadIdx.x;
    wsh[t]       = w4[t];
    wsh[t + 256] = w4[t + 256];
    __syncthreads();
    int warp = t >> 5, lane = t & 31;
    int r = blockIdx.x*8 + warp;
    const float* h = d_H3 + (size_t)r*H3DIM;
    float s0 = 0.f, s1 = 0.f;
    for (int c = lane; c < H3DIM; c += 32) {
        float hv = h[c];
        s0 = fmaf(hv, wsh[c*2+0], s0);
        s1 = fmaf(hv, wsh[c*2+1], s1);
    }
#pragma unroll
    for (int o = 16; o; o >>= 1) {
        s0 += __shfl_xor_sync(0xffffffffu, s0, o);
        s1 += __shfl_xor_sync(0xffffffffu, s1, o);
    }
    if (lane == 0) {
        out[r*2 + 0] = s0 + b4[0];
        out[r*2 + 1] = s1 + b4[1];
    }
}

// ---------------- launch -----------------------------------------------------
extern "C" void kernel_launch(void* const* d_in, const int* in_sizes, int n_in,
                              void* d_out, int out_size) {
    const float* x      = (const float*)d_in[0];
    const float* thr    = (const float*)d_in[1];
    const float* w1     = (const float*)d_in[2];
    const float* b1     = (const float*)d_in[3];
    const float* w2     = (const float*)d_in[4];
    const float* b2     = (const float*)d_in[5];
    const float* w3     = (const float*)d_in[6];
    const float* b3     = (const float*)d_in[7];
    const float* w4     = (const float*)d_in[8];
    const float* b4     = (const float*)d_in[9];
    const int*   starts = (const int*)d_in[10];
    float* out = (float*)d_out;

    // preprocessing
    k_emb<<<BSZ*NEN, 256>>>(x, starts);
    k_pairs<<<1, 64>>>();
    dim3 gcos(NEN, BSZ);
    k_cos<<<gcos, 256>>>();
    k_std<<<BSZ, 256>>>();

    // weight plane expansions (tiny; outputs resolved device-side)
    k_expand_w1_t<<<(1536*HSZ + 255)/256, 256>>>(w1);
    k_expand_t<<<(HSZ*H2DIM + 255)/256, 256>>>(w2, 1, HSZ, H2DIM);
    k_expand_t<<<(H2DIM*H3DIM + 255)/256, 256>>>(w3, 2, H2DIM, H3DIM);

    // G = emb @ [w1a|w1b]   (1024 x 1536, K'=2304) -> d_G fp32
    {
        dim3 g(1536/128, (BSZ*NEN)/128);     // (12, 8)
        gemm_bf16<<<g, 256>>>(0, 0, nullptr, 0, BSZ*NEN, 1536, K1X);
    }

    // H1 assembly -> plane-split bf16
    k_h1<<<NROWS, 384>>>(w1, b1, thr);

    // layer 2: H2x = split(relu(H1 @ w2 + b2))   (32256 x 512, K'=2304)
    {
        dim3 g(H2DIM/128, NROWS/128);        // (4, 252)
        gemm_bf16<<<g, 256>>>(1, 1, b2, 1, NROWS, H2DIM, K1X);
    }
    // layer 3: H3 = relu(H2 @ w3 + b3) fp32   (32256 x 256, K'=1536)
    {
        dim3 g(H3DIM/128, NROWS/128);        // (2, 252)
        gemm_bf16<<<g, 256>>>(2, 2, b3, 2, NROWS, H3DIM, K2X);
    }
    // layer 4
    k_out<<<NROWS/8, 256>>>(w4, b4, out);
}

// round 10
// speedup vs baseline: 2.5560x; 1.2515x over previous
#include <cuda_runtime.h>
#include <cuda_bf16.h>
#include <math.h>
#include <stdint.h>

// Problem constants
#define BSZ   16
#define LSZ   2048
#define HSZ   768
#define NEN   64
#define SPAN  4
#define NPAIR 2016
#define NROWS (BSZ*NPAIR)          // 32256
#define H2DIM 512
#define H3DIM 256

// ---------------- scratch (device globals; resolved ONLY in device code) -----
__device__ __align__(16) float d_nrm[BSZ*NEN*HSZ];
__device__ __align__(16) float d_cos[BSZ*NEN*NEN];
__device__ float d_std[BSZ];
__device__ int   d_pi[NPAIR];
__device__ int   d_pj[NPAIR];
// A and B operands both stored as [h-plane | l-plane] (2K bf16 per row).
__device__ __align__(16) __nv_bfloat16 d_embX[BSZ*NEN*2*HSZ];        // [1024][1536]
__device__ __align__(16) __nv_bfloat16 d_w1x [1536*2*HSZ];           // [1536][1536]
__device__ __align__(16) __nv_bfloat16 d_w2x [H2DIM*2*HSZ];          // [512][1536]
__device__ __align__(16) __nv_bfloat16 d_w3x [H3DIM*2*H2DIM];        // [256][1024]
__device__ __align__(16) float d_G [(size_t)BSZ*NEN*1536];           // [G1|G2]
__device__ __align__(16) __nv_bfloat16 d_H1x[(size_t)NROWS*2*HSZ];   // [32256][1536]
__device__ __align__(16) __nv_bfloat16 d_H2x[(size_t)NROWS*2*H2DIM]; // [32256][1024]
__device__ __align__(16) float d_H3[(size_t)NROWS*H3DIM];

__device__ __forceinline__ const __nv_bfloat16* selA(int s) {
    return s == 0 ? d_embX : (s == 1 ? d_H1x : d_H2x);
}
__device__ __forceinline__ const __nv_bfloat16* selB(int s) {
    return s == 0 ? d_w1x : (s == 1 ? d_w2x : d_w3x);
}
__device__ __forceinline__ __nv_bfloat16* selWout(int s) {
    return s == 1 ? d_w2x : d_w3x;
}

// ---------------- helpers ----------------------------------------------------
__device__ __forceinline__ uint32_t smem_u32(const void* p) {
    return (uint32_t)__cvta_generic_to_shared(p);
}
#define CP16(dst, src) asm volatile("cp.async.cg.shared.global [%0], [%1], 16;\n" :: "r"(dst), "l"(src))
#define CP_COMMIT()    asm volatile("cp.async.commit_group;\n" ::: "memory")
#define CP_WAIT1()     asm volatile("cp.async.wait_group 1;\n" ::: "memory")
#define CP_WAIT0()     asm volatile("cp.async.wait_group 0;\n" ::: "memory")

__device__ __forceinline__ uint32_t pack_bf2(__nv_bfloat16 a, __nv_bfloat16 b) {
    __nv_bfloat162 t = __nv_bfloat162(a, b);    // a = low 16 bits
    uint32_t u; memcpy(&u, &t, 4); return u;
}
__device__ __forceinline__ void split_bf(float v, __nv_bfloat16& h, __nv_bfloat16& l) {
    h = __float2bfloat16_rn(v);
    l = __float2bfloat16_rn(v - __bfloat162float(h));
}

// ---------------- K1: span max-pool + normalize + [h|l] split ----------------
__global__ void k_emb(const float* __restrict__ x, const int* __restrict__ starts) {
    int be = blockIdx.x;
    int b  = be / NEN;
    int e  = be - b*NEN;
    int s0 = starts[b*NEN + e];
    const float* xb = x + ((size_t)b*LSZ + s0) * HSZ;
    int t = threadIdx.x;                 // 256
    float v[3];
    float ss = 0.f;
#pragma unroll
    for (int r = 0; r < 3; r++) {
        int c = t + r*256;
        float m = xb[c];
        m = fmaxf(m, xb[HSZ   + c]);
        m = fmaxf(m, xb[2*HSZ + c]);
        m = fmaxf(m, xb[3*HSZ + c]);
        v[r] = m;
        ss += m*m;
    }
    __shared__ float red[256];
    red[t] = ss;
    __syncthreads();
    for (int o = 128; o > 0; o >>= 1) {
        if (t < o) red[t] += red[t + o];
        __syncthreads();
    }
    __shared__ float s_inv;
    if (t == 0) s_inv = 1.0f / fmaxf(sqrtf(red[0]), 1e-8f);
    __syncthreads();
    float iv = s_inv;
    __nv_bfloat16* ex = d_embX + (size_t)be*2*HSZ;
#pragma unroll
    for (int r = 0; r < 3; r++) {
        int c = t + r*256;
        d_nrm[be*HSZ + c] = v[r] * iv;
        __nv_bfloat16 h, l; split_bf(v[r], h, l);
        ex[c]       = h;
        ex[HSZ + c] = l;
    }
}

// ---------------- K2: pair tables --------------------------------------------
__global__ void k_pairs() {
    int i = threadIdx.x;
    if (i >= NEN - 1) return;
    int off = i*63 - i*(i-1)/2;
    for (int j = i + 1; j < NEN; j++) { d_pi[off] = i; d_pj[off] = j; off++; }
}

// ---------------- K3: cosine matrix ------------------------------------------
__global__ void k_cos() {
    int i = blockIdx.x, b = blockIdx.y;
    __shared__ float ni[HSZ];
    int t = threadIdx.x;
    const float* base = d_nrm + (b*NEN + i)*HSZ;
#pragma unroll
    for (int r = 0; r < 3; r++) ni[t + r*256] = base[t + r*256];
    __syncthreads();
    int warp = t >> 5, lane = t & 31;
    for (int j = warp; j < NEN; j += 8) {
        const float* nj = d_nrm + (b*NEN + j)*HSZ;
        float s = 0.f;
        for (int c = lane; c < HSZ; c += 32) s += ni[c] * nj[c];
#pragma unroll
        for (int o = 16; o; o >>= 1) s += __shfl_xor_sync(0xffffffffu, s, o);
        if (lane == 0) d_cos[(b*NEN + i)*NEN + j] = s;
    }
}

// ---------------- K4: unbiased std -------------------------------------------
__global__ void k_std() {
    int b = blockIdx.x, t = threadIdx.x;
    double s = 0.0, s2 = 0.0;
    for (int k = t; k < NEN*NEN; k += 256) {
        double v = (double)d_cos[b*NEN*NEN + k];
        s += v; s2 += v*v;
    }
    __shared__ double rs[256], rq[256];
    rs[t] = s; rq[t] = s2;
    __syncthreads();
    for (int o = 128; o > 0; o >>= 1) {
        if (t < o) { rs[t] += rs[t+o]; rq[t] += rq[t+o]; }
        __syncthreads();
    }
    if (t == 0) {
        double n = (double)(NEN*NEN);
        double var = (rq[0] - rs[0]*rs[0]/n) / (n - 1.0);
        if (var < 0.0) var = 0.0;
        d_std[b] = (float)sqrt(var);
    }
}

// ---------------- weight transpose + [h|l] split ------------------------------
// W: [K][N] row-major -> Out(sel): [N][2K] planes [h | l]
__global__ void k_expand_t(const float* __restrict__ W, int selOut, int K, int N) {
    __nv_bfloat16* Out = selWout(selOut);
    int idx = blockIdx.x*256 + threadIdx.x;
    if (idx >= K*N) return;
    int n = idx / K, k = idx - n*K;
    __nv_bfloat16 h, l; split_bf(W[(size_t)k*N + n], h, l);
    __nv_bfloat16* o = Out + (size_t)n*2*K;
    o[k]     = h;
    o[K + k] = l;
}
// combined [w1a | w1b] transposed -> d_w1x [1536][2*768] planes [h|l]
__global__ void k_expand_w1_t(const float* __restrict__ w1) {
    int idx = blockIdx.x*256 + threadIdx.x;
    if (idx >= 1536*HSZ) return;
    int n = idx / HSZ, k = idx - n*HSZ;
    float v = (n < HSZ) ? w1[(size_t)(1+k)*HSZ + n]
                        : w1[(size_t)(769+k)*HSZ + (n-HSZ)];
    __nv_bfloat16 h, l; split_bf(v, h, l);
    __nv_bfloat16* o = d_w1x + (size_t)n*2*HSZ;
    o[k]       = h;
    o[HSZ + k] = l;
}

// ---------------- bf16 tensor-core GEMM (3-term split, shared fragments) -----
// D = act(Ah Bh^T + Ah Bl^T + Al Bh^T + bias).  A: [M][2K], B: [N][2K].
// outMode 0: d_G fp32 (no relu/bias). 1: d_H2x [h|l] planes (relu+bias).
// 2: d_H3 fp32 (relu+bias).
// BM=BN=128, BK=32, 256 threads, warp tile 64x32, double-buffered cp.async.
// Stage: Ah[128][40] Al[128][40] Bh[128][40] Bl[128][40] bf16 = 40960 B.
#define STG_ELEMS  20480
#define AH_OFF     0
#define AL_OFF     5120
#define BH_OFF     10240
#define BL_OFF     15360
#define SMEM_GEMM  (2*STG_ELEMS*2)            // 81920 bytes

__global__ __launch_bounds__(256, 2)
void gemm_bf16(int selA_i, int selB_i, const float* __restrict__ bias,
               int outMode, int M, int N, int K) {
    extern __shared__ __align__(16) __nv_bfloat16 sm[];
    const __nv_bfloat16* A  = selA(selA_i);
    const __nv_bfloat16* Bt = selB(selB_i);
    float* Cf = (outMode == 0) ? d_G : d_H3;
    __nv_bfloat16* Cx = (outMode == 1) ? d_H2x : nullptr;
    int relu = (outMode != 0);
    int len = 2*K;                       // row length of both A and B

    int tid = threadIdx.x;
    int bm = blockIdx.y * 128;
    int bn = blockIdx.x * 128;
    int lane = tid & 31, w = tid >> 5;
    int wm = w & 1, wn = w >> 1;
    const int m_off = wm*64, n_off = wn*32;
    int gid = lane >> 2, tig = lane & 3;

    float acc[4][4][4];
#pragma unroll
    for (int i = 0; i < 4; i++)
#pragma unroll
        for (int j = 0; j < 4; j++)
#pragma unroll
            for (int q = 0; q < 4; q++) acc[i][j][q] = 0.f;

    int nk = K >> 5;

    // prefetch tile 0 into stage 0
#pragma unroll
    for (int rr = 0; rr < 2; rr++) {
        int q = tid + rr*256;
        int row = q >> 2, c8 = (q & 3)*8;
        CP16(smem_u32(&sm[AH_OFF + row*40 + c8]), A  + (size_t)(bm + row)*len + c8);
        CP16(smem_u32(&sm[AL_OFF + row*40 + c8]), A  + (size_t)(bm + row)*len + K + c8);
        CP16(smem_u32(&sm[BH_OFF + row*40 + c8]), Bt + (size_t)(bn + row)*len + c8);
        CP16(smem_u32(&sm[BL_OFF + row*40 + c8]), Bt + (size_t)(bn + row)*len + K + c8);
    }
    CP_COMMIT();

    for (int kt = 0; kt < nk; kt++) {
        int cur = kt & 1;
        const __nv_bfloat16* st = sm + cur*STG_ELEMS;
        if (kt + 1 < nk) {
            int k0 = (kt + 1) << 5;
            __nv_bfloat16* nx = (__nv_bfloat16*)sm + (cur ^ 1)*STG_ELEMS;
#pragma unroll
            for (int rr = 0; rr < 2; rr++) {
                int q = tid + rr*256;
                int row = q >> 2, c8 = (q & 3)*8;
                CP16(smem_u32(&nx[AH_OFF + row*40 + c8]), A  + (size_t)(bm + row)*len + k0 + c8);
                CP16(smem_u32(&nx[AL_OFF + row*40 + c8]), A  + (size_t)(bm + row)*len + K + k0 + c8);
                CP16(smem_u32(&nx[BH_OFF + row*40 + c8]), Bt + (size_t)(bn + row)*len + k0 + c8);
                CP16(smem_u32(&nx[BL_OFF + row*40 + c8]), Bt + (size_t)(bn + row)*len + K + k0 + c8);
            }
            CP_COMMIT();
            CP_WAIT1();          // tile kt's group complete; kt+1 in flight
        } else {
            CP_WAIT0();          // tail: drain everything
        }
        __syncthreads();

#pragma unroll
        for (int kk = 0; kk < 2; kk++) {
            int kc = kk*16 + tig*2;
            // B fragments: both planes resident
            uint32_t bh[4][2], bl[4][2];
#pragma unroll
            for (int nj = 0; nj < 4; nj++) {
                const __nv_bfloat16* pbh = &st[BH_OFF + (n_off + nj*8 + gid)*40 + kc];
                const __nv_bfloat16* pbl = &st[BL_OFF + (n_off + nj*8 + gid)*40 + kc];
                bh[nj][0] = *(const uint32_t*)(pbh);
                bh[nj][1] = *(const uint32_t*)(pbh + 8);
                bl[nj][0] = *(const uint32_t*)(pbl);
                bl[nj][1] = *(const uint32_t*)(pbl + 8);
            }
            // A fragments: one plane at a time (register budget)
            uint32_t af[4][4];
#pragma unroll
            for (int mi = 0; mi < 4; mi++) {
                const __nv_bfloat16* pa = &st[AH_OFF + (m_off + mi*16 + gid)*40 + kc];
                af[mi][0] = *(const uint32_t*)(pa);
                af[mi][1] = *(const uint32_t*)(pa + 8*40);
                af[mi][2] = *(const uint32_t*)(pa + 8);
                af[mi][3] = *(const uint32_t*)(pa + 8*40 + 8);
            }
            // pass 1: Ah * Bh
#pragma unroll
            for (int mi = 0; mi < 4; mi++)
#pragma unroll
                for (int nj = 0; nj < 4; nj++)
                    asm volatile(
                        "mma.sync.aligned.m16n8k16.row.col.f32.bf16.bf16.f32 "
                        "{%0,%1,%2,%3}, {%4,%5,%6,%7}, {%8,%9}, {%0,%1,%2,%3};"
                        : "+f"(acc[mi][nj][0]), "+f"(acc[mi][nj][1]),
                          "+f"(acc[mi][nj][2]), "+f"(acc[mi][nj][3])
                        : "r"(af[mi][0]), "r"(af[mi][1]), "r"(af[mi][2]), "r"(af[mi][3]),
                          "r"(bh[nj][0]), "r"(bh[nj][1]));
            // pass 2: Ah * Bl  (reuse af)
#pragma unroll
            for (int mi = 0; mi < 4; mi++)
#pragma unroll
                for (int nj = 0; nj < 4; nj++)
                    asm volatile(
                        "mma.sync.aligned.m16n8k16.row.col.f32.bf16.bf16.f32 "
                        "{%0,%1,%2,%3}, {%4,%5,%6,%7}, {%8,%9}, {%0,%1,%2,%3};"
                        : "+f"(acc[mi][nj][0]), "+f"(acc[mi][nj][1]),
                          "+f"(acc[mi][nj][2]), "+f"(acc[mi][nj][3])
                        : "r"(af[mi][0]), "r"(af[mi][1]), "r"(af[mi][2]), "r"(af[mi][3]),
                          "r"(bl[nj][0]), "r"(bl[nj][1]));
            // pass 3: Al * Bh  (reload A fragments, reuse bh)
#pragma unroll
            for (int mi = 0; mi < 4; mi++) {
                const __nv_bfloat16* pa = &st[AL_OFF + (m_off + mi*16 + gid)*40 + kc];
                af[mi][0] = *(const uint32_t*)(pa);
                af[mi][1] = *(const uint32_t*)(pa + 8*40);
                af[mi][2] = *(const uint32_t*)(pa + 8);
                af[mi][3] = *(const uint32_t*)(pa + 8*40 + 8);
            }
#pragma unroll
            for (int mi = 0; mi < 4; mi++)
#pragma unroll
                for (int nj = 0; nj < 4; nj++)
                    asm volatile(
                        "mma.sync.aligned.m16n8k16.row.col.f32.bf16.bf16.f32 "
                        "{%0,%1,%2,%3}, {%4,%5,%6,%7}, {%8,%9}, {%0,%1,%2,%3};"
                        : "+f"(acc[mi][nj][0]), "+f"(acc[mi][nj][1]),
                          "+f"(acc[mi][nj][2]), "+f"(acc[mi][nj][3])
                        : "r"(af[mi][0]), "r"(af[mi][1]), "r"(af[mi][2]), "r"(af[mi][3]),
                          "r"(bh[nj][0]), "r"(bh[nj][1]));
        }
        __syncthreads();
    }

    // epilogue
#pragma unroll
    for (int mi = 0; mi < 4; mi++) {
        int r0 = bm + m_off + mi*16 + gid;
#pragma unroll
        for (int nj = 0; nj < 4; nj++) {
            int c = bn + n_off + nj*8 + tig*2;
            float bb0 = bias ? bias[c]   : 0.f;
            float bb1 = bias ? bias[c+1] : 0.f;
#pragma unroll
            for (int half = 0; half < 2; half++) {
                int r = r0 + half*8;
                float v0 = acc[mi][nj][half*2+0] + bb0;
                float v1 = acc[mi][nj][half*2+1] + bb1;
                if (relu) { v0 = fmaxf(v0, 0.f); v1 = fmaxf(v1, 0.f); }
                if (Cx) {
                    // [h|l] planes, row length 2N
                    __nv_bfloat16 h0, l0, h1, l1;
                    split_bf(v0, h0, l0);
                    split_bf(v1, h1, l1);
                    uint32_t* po = (uint32_t*)Cx;
                    size_t rb = (size_t)r*2*N;
                    po[(rb +     c) >> 1] = pack_bf2(h0, h1);
                    po[(rb + N + c) >> 1] = pack_bf2(l0, l1);
                } else {
                    float2 v; v.x = v0; v.y = v1;
                    *(float2*)&Cf[(size_t)r*N + c] = v;
                }
            }
        }
    }
}

// ---------------- K5: assemble [h|l] H1 --------------------------------------
__global__ void k_h1(const float* __restrict__ w1, const float* __restrict__ b1,
                     const float* __restrict__ thr) {
    int r = blockIdx.x;
    int b = r / NPAIR;
    int p = r - b*NPAIR;
    int i = d_pi[p], j = d_pj[p];
    float sim = (d_cos[(b*NEN + i)*NEN + j] - thr[0]) / (d_std[b] + 1e-5f);
    const float* g1 = d_G + (size_t)(b*NEN + i)*1536;
    const float* g2 = d_G + (size_t)(b*NEN + j)*1536 + HSZ;
    uint32_t* po = (uint32_t*)(d_H1x + (size_t)r*2*HSZ);
    int pidx = threadIdx.x;              // 384 threads, one col-pair each
    int c = pidx*2;
    float v0 = fmaxf(g1[c]   + g2[c]   + sim*w1[c]   + b1[c],   0.f);
    float v1 = fmaxf(g1[c+1] + g2[c+1] + sim*w1[c+1] + b1[c+1], 0.f);
    __nv_bfloat16 h0, l0, h1, l1;
    split_bf(v0, h0, l0);
    split_bf(v1, h1, l1);
    po[pidx]              = pack_bf2(h0, h1);  // h-plane
    po[(HSZ >> 1) + pidx] = pack_bf2(l0, l1);  // l-plane
}

// ---------------- K6: final tiny layer ---------------------------------------
__global__ void k_out(const float* __restrict__ w4, const float* __restrict__ b4,
                      float* __restrict__ out) {
    __shared__ float wsh[H3DIM*2];
    int t = threadIdx.x;
    wsh[t]       = w4[t];
    wsh[t + 256] = w4[t + 256];
    __syncthreads();
    int warp = t >> 5, lane = t & 31;
    int r = blockIdx.x*8 + warp;
    const float* h = d_H3 + (size_t)r*H3DIM;
    float s0 = 0.f, s1 = 0.f;
    for (int c = lane; c < H3DIM; c += 32) {
        float hv = h[c];
        s0 = fmaf(hv, wsh[c*2+0], s0);
        s1 = fmaf(hv, wsh[c*2+1], s1);
    }
#pragma unroll
    for (int o = 16; o; o >>= 1) {
        s0 += __shfl_xor_sync(0xffffffffu, s0, o);
        s1 += __shfl_xor_sync(0xffffffffu, s1, o);
    }
    if (lane == 0) {
        out[r*2 + 0] = s0 + b4[0];
        out[r*2 + 1] = s1 + b4[1];
    }
}

// ---------------- launch -----------------------------------------------------
extern "C" void kernel_launch(void* const* d_in, const int* in_sizes, int n_in,
                              void* d_out, int out_size) {
    const float* x      = (const float*)d_in[0];
    const float* thr    = (const float*)d_in[1];
    const float* w1     = (const float*)d_in[2];
    const float* b1     = (const float*)d_in[3];
    const float* w2     = (const float*)d_in[4];
    const float* b2     = (const float*)d_in[5];
    const float* w3     = (const float*)d_in[6];
    const float* b3     = (const float*)d_in[7];
    const float* w4     = (const float*)d_in[8];
    const float* b4     = (const float*)d_in[9];
    const int*   starts = (const int*)d_in[10];
    float* out = (float*)d_out;

    cudaFuncSetAttribute(gemm_bf16, cudaFuncAttributeMaxDynamicSharedMemorySize,
                         SMEM_GEMM);

    // preprocessing
    k_emb<<<BSZ*NEN, 256>>>(x, starts);
    k_pairs<<<1, 64>>>();
    dim3 gcos(NEN, BSZ);
    k_cos<<<gcos, 256>>>();
    k_std<<<BSZ, 256>>>();

    // weight transposes + [h|l] split
    k_expand_w1_t<<<(1536*HSZ + 255)/256, 256>>>(w1);
    k_expand_t<<<(HSZ*H2DIM + 255)/256, 256>>>(w2, 1, HSZ, H2DIM);
    k_expand_t<<<(H2DIM*H3DIM + 255)/256, 256>>>(w3, 2, H2DIM, H3DIM);

    // G = emb @ [w1a|w1b]   (1024 x 1536, K=768) -> d_G fp32
    {
        dim3 g(1536/128, (BSZ*NEN)/128);     // (12, 8)
        gemm_bf16<<<g, 256, SMEM_GEMM>>>(0, 0, nullptr, 0, BSZ*NEN, 1536, HSZ);
    }

    // H1 assembly -> [h|l] bf16
    k_h1<<<NROWS, 384>>>(w1, b1, thr);

    // layer 2: H2x = split(relu(H1 @ w2 + b2))   (32256 x 512, K=768)
    {
        dim3 g(H2DIM/128, NROWS/128);        // (4, 252)
        gemm_bf16<<<g, 256, SMEM_GEMM>>>(1, 1, b2, 1, NROWS, H2DIM, HSZ);
    }
    // layer 3: H3 = relu(H2 @ w3 + b3) fp32   (32256 x 256, K=512)
    {
        dim3 g(H3DIM/128, NROWS/128);        // (2, 252)
        gemm_bf16<<<g, 256, SMEM_GEMM>>>(2, 2, b3, 2, NROWS, H3DIM, H2DIM);
    }
    // layer 4
    k_out<<<NROWS/8, 256>>>(w4, b4, out);
}